// round 1
// baseline (speedup 1.0000x reference)
#include <cuda_runtime.h>

// EM-routing capsule layer.
// B=64, S=14, I=32 -> N = 196*32 = 6272 poses per batch, C=10 classes, D=16.
//
// Strategy: never materialize votes. Each routing iteration is one fused
// streaming pass over inputs_pose. rr is recomputed on the fly from the
// previous iteration's per-class statistics (tiny). Warp = class, lane = i.

#define BB   64
#define SSQ  196      // S*S
#define II   32
#define CCL  10
#define KB   4        // spatial slices per batch (196/4 = 49 s per CTA)
#define SPC  49
#define EPSf 1e-9f

// scratch (no allocations allowed)
__device__ float g_partial[BB * KB * CCL * 34]; // per (b,slice,c): [0]=rsum [1..16]=sv [17..32]=sv2
__device__ float g_stats[BB * CCL * 34];        // per (b,c): [0..15]=mean [16..31]=1/(2var+eps) [32]=cst

template<int IT>
__global__ __launch_bounds__(320, 1)
void accum_kernel(const float* __restrict__ pose,
                  const float* __restrict__ act,
                  const float* __restrict__ w)
{
    const int b    = blockIdx.x / KB;
    const int sl   = blockIdx.x % KB;
    const int c    = threadIdx.x >> 5;   // warp id = class
    const int lane = threadIdx.x & 31;   // lane    = capsule i

    __shared__ float s_zz[32 * 11];      // [n_loc][c], stride 11 -> conflict-free
    __shared__ float s_rr[32 * 11];

    // W[i=lane][c] : 4x4 in registers
    float W[16];
    {
        const float4* wp = reinterpret_cast<const float4*>(w + (lane * CCL + c) * 16);
        #pragma unroll
        for (int q = 0; q < 4; q++) {
            float4 t = wp[q];
            W[q*4+0] = t.x; W[q*4+1] = t.y; W[q*4+2] = t.z; W[q*4+3] = t.w;
        }
    }

    float m[16], inv[16], cstc = 0.f;
    if (IT > 0) {
        const float* st = g_stats + (b * CCL + c) * 34;
        #pragma unroll
        for (int d = 0; d < 16; d++) { m[d] = st[d]; inv[d] = st[16 + d]; }
        cstc = st[32];
    }

    float sv[16], sv2[16];
    #pragma unroll
    for (int d = 0; d < 16; d++) { sv[d] = 0.f; sv2[d] = 0.f; }
    float rsum = 0.f;

    const int s0 = sl * SPC;
    for (int s = s0; s < s0 + SPC; ++s) {
        const int h  = s / 14;
        const int wx = s - h * 14;
        const float cr = (h  + 0.5f) * (1.0f / 14.0f);
        const float cw = (wx + 0.5f) * (1.0f / 14.0f);

        const int nbase = (b * SSQ + s) * II;

        // pose row for n = s*32 + lane : 16 floats
        float p16[16];
        {
            const float4* pv = reinterpret_cast<const float4*>(pose + (size_t)(nbase + lane) * 16);
            #pragma unroll
            for (int q4 = 0; q4 < 4; q4++) {
                float4 t = pv[q4];
                p16[q4*4+0] = t.x; p16[q4*4+1] = t.y; p16[q4*4+2] = t.z; p16[q4*4+3] = t.w;
            }
        }
        float a = 0.f;
        if (IT == 0 || c == 0) a = act[nbase + lane];

        // votes: v = pose(4x4) @ W(4x4), plus coordinate addition on d=0,1
        float v[16];
        #pragma unroll
        for (int p = 0; p < 4; p++) {
            #pragma unroll
            for (int r = 0; r < 4; r++) {
                float acc =      p16[p*4+0] * W[0*4+r];
                acc = fmaf(p16[p*4+1], W[1*4+r], acc);
                acc = fmaf(p16[p*4+2], W[2*4+r], acc);
                acc = fmaf(p16[p*4+3], W[3*4+r], acc);
                v[p*4+r] = acc;
            }
        }
        v[0] += cr;
        v[1] += cw;

        float rrp;
        if (IT > 0) {
            // zz[n][c] = cst[c] - sum_d (v-m)^2 * inv(2var+eps)
            float accz = 0.f;
            #pragma unroll
            for (int d = 0; d < 16; d++) {
                float t = v[d] - m[d];
                accz = fmaf(t * inv[d], t, accz);
            }
            s_zz[lane * 11 + c] = cstc - accz;
            __syncthreads();

            if (c == 0) {            // warp 0: dense softmax, lane = n_loc
                float z[10];
                float mx = -1e30f;
                #pragma unroll
                for (int j = 0; j < 10; j++) { z[j] = s_zz[lane * 11 + j]; mx = fmaxf(mx, z[j]); }
                float Z = 0.f;
                #pragma unroll
                for (int j = 0; j < 10; j++) { z[j] = __expf(z[j] - mx); Z += z[j]; }
                float sc = a / Z;    // fold activation into rr_p
                #pragma unroll
                for (int j = 0; j < 10; j++) s_rr[lane * 11 + j] = z[j] * sc;
            }
            __syncthreads();
            rrp = s_rr[lane * 11 + c];
        } else {
            rrp = a * 0.1f;          // uniform rr = 1/C
        }

        rsum += rrp;
        #pragma unroll
        for (int d = 0; d < 16; d++) {
            float rv = rrp * v[d];
            sv[d] += rv;
            sv2[d] = fmaf(rv, v[d], sv2[d]);
        }
    }

    // reduce over the 32 lanes (over i)
    #pragma unroll
    for (int off = 16; off > 0; off >>= 1) {
        rsum += __shfl_xor_sync(0xffffffffu, rsum, off);
        #pragma unroll
        for (int d = 0; d < 16; d++) {
            sv[d]  += __shfl_xor_sync(0xffffffffu, sv[d],  off);
            sv2[d] += __shfl_xor_sync(0xffffffffu, sv2[d], off);
        }
    }
    if (lane == 0) {
        float* o = g_partial + ((b * KB + sl) * CCL + c) * 34;
        o[0] = rsum;
        #pragma unroll
        for (int d = 0; d < 16; d++) { o[1 + d] = sv[d]; o[17 + d] = sv2[d]; }
    }
}

template<int IT>
__global__ __launch_bounds__(160)
void finalize_kernel(const float* __restrict__ beta_v,
                     const float* __restrict__ beta_a,
                     float* __restrict__ out)
{
    const int b = blockIdx.x;
    const int c = threadIdx.x >> 4;
    const int d = threadIdx.x & 15;

    float rsum = 0.f, sv = 0.f, sv2 = 0.f;
    #pragma unroll
    for (int sl = 0; sl < KB; sl++) {
        const float* p = g_partial + ((b * KB + sl) * CCL + c) * 34;
        rsum += p[0];
        sv   += p[1 + d];
        sv2  += p[17 + d];
    }

    float mean = sv / rsum;
    float var  = fmaxf(sv2 / rsum - mean * mean, 0.f);
    float stdv = sqrtf(var);
    float lg   = __logf(stdv + EPSf);

    float cost = (beta_v[c] + lg) * rsum;   // per-(c,d) term of cost
    float lgs  = lg;
    #pragma unroll
    for (int off = 8; off > 0; off >>= 1) { // reduce over the 16 d's
        cost += __shfl_xor_sync(0xffffffffu, cost, off, 16);
        lgs  += __shfl_xor_sync(0xffffffffu, lgs,  off, 16);
    }

    const float invT = 1.0f + (float)IT;    // schedule: 1, 2, 3
    float oact = 1.0f / (1.0f + __expf(-invT * (beta_a[c] - cost)));

    if (IT < 2) {
        float* st = g_stats + (b * CCL + c) * 34;
        st[d]      = mean;
        st[16 + d] = 1.0f / (2.0f * var + EPSf);
        if (d == 0) st[32] = __logf(oact + EPSf) - lgs;
    } else {
        out[(b * CCL + c) * 16 + d] = mean;                 // pose [B,C,4,4]
        if (d == 0) out[BB * CCL * 16 + b * CCL + c] = oact; // act  [B,C]
    }
}

extern "C" void kernel_launch(void* const* d_in, const int* in_sizes, int n_in,
                              void* d_out, int out_size)
{
    const float* pose = (const float*)d_in[0];
    const float* act  = (const float*)d_in[1];
    const float* w    = (const float*)d_in[2];
    const float* bv   = (const float*)d_in[3];
    const float* ba   = (const float*)d_in[4];
    float* out = (float*)d_out;

    dim3 ga(BB * KB), ba_(320), gf(BB), bf(160);

    accum_kernel<0><<<ga, ba_>>>(pose, act, w);
    finalize_kernel<0><<<gf, bf>>>(bv, ba, out);
    accum_kernel<1><<<ga, ba_>>>(pose, act, w);
    finalize_kernel<1><<<gf, bf>>>(bv, ba, out);
    accum_kernel<2><<<ga, ba_>>>(pose, act, w);
    finalize_kernel<2><<<gf, bf>>>(bv, ba, out);
}